// round 16
// baseline (speedup 1.0000x reference)
#include <cuda_runtime.h>
#include <cstdint>

#define NA 200000
#define NW 50000
#define D 256
#define P 64
#define E_TIC 4000000
#define E_REL 1000000

#define NB_TIC ((NA + 2047) / 2048)   // 98
#define NB_REL ((NW + 2047) / 2048)   // 25

typedef unsigned long long u64;
typedef unsigned int u32;

// ---------------- scratch (device globals: no allocation allowed) ----------
__device__ float g_h_tic[(size_t)NA * P];
__device__ float g_h_rel[(size_t)NA * P];
__device__ float g_acc_tic[(size_t)NA * P];
__device__ float g_acc_rel[(size_t)NW * P];

__device__ int  g_cnt_tic[NA];
__device__ int  g_cnt_rel[NW];
__device__ int  g_start_tic[NA];
__device__ int  g_start_rel[NW];
__device__ int  g_pos_tic[NA];
__device__ int  g_pos_rel[NW];
__device__ int  g_bsum_tic[128];
__device__ int  g_bsum_rel[128];
__device__ u64  g_csr_tic[E_TIC];           // packed (w<<32 | src)
__device__ u64  g_csr_rel[E_REL];

// ---------------- helpers ---------------------------------------------------
__device__ __forceinline__ u32 f2tf32(float f) {
    u32 o; asm("cvt.rna.tf32.f32 %0, %1;" : "=r"(o) : "f"(f)); return o;
}

__device__ __forceinline__ void mma_tf32(float* c, const u32* a, const u32* b) {
    asm volatile(
        "mma.sync.aligned.m16n8k8.row.col.f32.tf32.tf32.f32 "
        "{%0,%1,%2,%3}, {%4,%5,%6,%7}, {%8,%9}, {%0,%1,%2,%3};"
        : "+f"(c[0]), "+f"(c[1]), "+f"(c[2]), "+f"(c[3])
        : "r"(a[0]), "r"(a[1]), "r"(a[2]), "r"(a[3]), "r"(b[0]), "r"(b[1]));
}

// ---------------- CSR build (R11-proven kernels) ----------------------------
template <int REL>
__global__ __launch_bounds__(256) void hist(const int* __restrict__ dst, int E) {
    int e4 = (blockIdx.x * blockDim.x + threadIdx.x) * 4;
    if (e4 >= E) return;
    int4 d = __ldg((const int4*)&dst[e4]);
    int* cnt = REL ? g_cnt_rel : g_cnt_tic;
    atomicAdd(&cnt[d.x], 1);
    atomicAdd(&cnt[d.y], 1);
    atomicAdd(&cnt[d.z], 1);
    atomicAdd(&cnt[d.w], 1);
}

template <int REL>
__global__ __launch_bounds__(256) void scan1() {
    const int N = REL ? NW : NA;
    const int* cnt = REL ? g_cnt_rel : g_cnt_tic;
    int* start = REL ? g_start_rel : g_start_tic;
    int* bsum = REL ? g_bsum_rel : g_bsum_tic;

    __shared__ int sh[256];
    int t = threadIdx.x;
    int base = blockIdx.x * 2048 + t * 8;
    int v[8]; int s = 0;
#pragma unroll
    for (int j = 0; j < 8; j++) {
        int idx = base + j;
        int c = (idx < N) ? cnt[idx] : 0;
        v[j] = s; s += c;
    }
    sh[t] = s;
    __syncthreads();
    int own = s;
    for (int off = 1; off < 256; off <<= 1) {
        int y = (t >= off) ? sh[t - off] : 0;
        __syncthreads();
        sh[t] += y;
        __syncthreads();
    }
    int texcl = sh[t] - own;
#pragma unroll
    for (int j = 0; j < 8; j++) {
        int idx = base + j;
        if (idx < N) start[idx] = v[j] + texcl;
    }
    if (t == 255) bsum[blockIdx.x] = sh[255];
}

template <int REL>
__global__ __launch_bounds__(128) void scan2() {
    const int NB = REL ? NB_REL : NB_TIC;
    int* bsum = REL ? g_bsum_rel : g_bsum_tic;
    __shared__ int sh[128];
    int t = threadIdx.x;
    int val = (t < NB) ? bsum[t] : 0;
    sh[t] = val;
    __syncthreads();
    for (int off = 1; off < 128; off <<= 1) {
        int y = (t >= off) ? sh[t - off] : 0;
        __syncthreads();
        sh[t] += y;
        __syncthreads();
    }
    if (t < NB) bsum[t] = sh[t] - val;
}

template <int REL>
__global__ __launch_bounds__(256) void scan3() {
    const int N = REL ? NW : NA;
    int* start = REL ? g_start_rel : g_start_tic;
    int* pos = REL ? g_pos_rel : g_pos_tic;
    const int* bsum = REL ? g_bsum_rel : g_bsum_tic;
    int add = bsum[blockIdx.x];
    int base = blockIdx.x * 2048 + threadIdx.x * 8;
#pragma unroll
    for (int j = 0; j < 8; j++) {
        int idx = base + j;
        if (idx < N) {
            int v = start[idx] + add;
            start[idx] = v;
            pos[idx] = v;
        }
    }
}

template <int REL>
__global__ __launch_bounds__(256) void reorder(const int* __restrict__ src,
                                               const int* __restrict__ dst,
                                               const float* __restrict__ we,
                                               int E) {
    int e4 = (blockIdx.x * blockDim.x + threadIdx.x) * 4;
    if (e4 >= E) return;
    int4 d = __ldg((const int4*)&dst[e4]);
    int4 s = __ldg((const int4*)&src[e4]);
    float4 w = __ldg((const float4*)&we[e4]);
    int* pos = REL ? g_pos_rel : g_pos_tic;
    u64* csr = REL ? g_csr_rel : g_csr_tic;
    int p0 = atomicAdd(&pos[d.x], 1);
    int p1 = atomicAdd(&pos[d.y], 1);
    int p2 = atomicAdd(&pos[d.z], 1);
    int p3 = atomicAdd(&pos[d.w], 1);
    csr[p0] = ((u64)__float_as_uint(w.x) << 32) | (u32)s.x;
    csr[p1] = ((u64)__float_as_uint(w.y) << 32) | (u32)s.y;
    csr[p2] = ((u64)__float_as_uint(w.z) << 32) | (u32)s.z;
    csr[p3] = ((u64)__float_as_uint(w.w) << 32) | (u32)s.w;
}

// ---------------- gather (R7 version): warp per dst row, mean ---------------
template <int REL>
__global__ __launch_bounds__(256) void gather_rows() {
    const int N = REL ? NW : NA;
    const int* start = REL ? g_start_rel : g_start_tic;
    const int* cnt = REL ? g_cnt_rel : g_cnt_tic;
    const u64* csr = REL ? g_csr_rel : g_csr_tic;
    const float* h = REL ? g_h_rel : g_h_tic;
    float* acc = REL ? g_acc_rel : g_acc_tic;

    int r = blockIdx.x * 8 + (threadIdx.x >> 5);
    int lid = threadIdx.x & 31;
    if (r >= N) return;
    int beg = start[r];
    int c = cnt[r];
    int end = beg + c;

    float ax = 0.f, ay = 0.f;
    int i = beg;
    for (; i + 4 <= end; i += 4) {
        u64 p0 = __ldg(&csr[i]);
        u64 p1 = __ldg(&csr[i + 1]);
        u64 p2 = __ldg(&csr[i + 2]);
        u64 p3 = __ldg(&csr[i + 3]);
        float2 h0 = *(const float2*)&h[(size_t)(u32)p0 * P + lid * 2];
        float2 h1 = *(const float2*)&h[(size_t)(u32)p1 * P + lid * 2];
        float2 h2 = *(const float2*)&h[(size_t)(u32)p2 * P + lid * 2];
        float2 h3 = *(const float2*)&h[(size_t)(u32)p3 * P + lid * 2];
        float w0 = __uint_as_float((u32)(p0 >> 32));
        float w1 = __uint_as_float((u32)(p1 >> 32));
        float w2 = __uint_as_float((u32)(p2 >> 32));
        float w3 = __uint_as_float((u32)(p3 >> 32));
        ax += h0.x * w0 + h1.x * w1 + h2.x * w2 + h3.x * w3;
        ay += h0.y * w0 + h1.y * w1 + h2.y * w2 + h3.y * w3;
    }
    for (; i < end; i++) {
        u64 p = __ldg(&csr[i]);
        float2 hv = *(const float2*)&h[(size_t)(u32)p * P + lid * 2];
        float w = __uint_as_float((u32)(p >> 32));
        ax += hv.x * w;
        ay += hv.y * w;
    }
    float inv = (c > 0) ? 1.0f / (float)c : 0.0f;
    float2 o; o.x = ax * inv; o.y = ay * inv;
    *(float2*)&acc[(size_t)r * P + lid * 2] = o;
}

// ---------------- epilogues -------------------------------------------------
__global__ __launch_bounds__(256) void epi_ac(float* __restrict__ out) {
    int i = blockIdx.x * blockDim.x + threadIdx.x;
    const int TOT = NA * P / 4;
    if (i >= TOT) return;
    float4 o = ((const float4*)out)[i];
    float4 a = ((const float4*)g_acc_tic)[i];
    o.x += a.x; o.y += a.y; o.z += a.z; o.w += a.w;
    ((float4*)out)[i] = o;
}

__global__ __launch_bounds__(256) void epi_w(const float* __restrict__ x,
                                             float* __restrict__ out) {
    int i = blockIdx.x * blockDim.x + threadIdx.x;
    const int TOT = NW * (P / 4);
    if (i >= TOT) return;
    int r = i >> 4, q = i & 15;
    float4 o = ((const float4*)out)[i];
    float4 a = ((const float4*)g_acc_rel)[i];
    float4 xv = *(const float4*)&x[(size_t)r * D + q * 4];
    o.x = 0.5f * (xv.x + o.x + a.x);
    o.y = 0.5f * (xv.y + o.y + a.y);
    o.z = 0.5f * (xv.z + o.z + a.z);
    o.w = 0.5f * (xv.w + o.w + a.w);
    ((float4*)out)[i] = o;
}

// ---------------- FUSED x_ac GEMM v2: BM=64, N=192 ---------------------------
// out cols: [0,64) -> g_h_tic, [64,128) -> g_h_rel, [128,192) -> out + b_tic.
// Register-fitted: MT=2, NT=6 -> 48 acc regs; launch_bounds caps at 128 regs.
__global__ __launch_bounds__(256, 2) void gemm_fused3(const float* __restrict__ x,
                                                      const float* __restrict__ Wnt,
                                                      const float* __restrict__ Wnr,
                                                      const float* __restrict__ Wst,
                                                      const float* __restrict__ b,
                                                      float* __restrict__ out,
                                                      int nrows) {
    constexpr int N_TILE = 192;
    constexpr int WM = 2, WN = 4;
    constexpr int WTM = 64 / WM;        // 32
    constexpr int WTN = N_TILE / WN;    // 48
    constexpr int MT = WTM / 16;        // 2
    constexpr int NT = WTN / 8;         // 6

    __shared__ u32 A_s[64][36];
    __shared__ u32 B_s[N_TILE][36];
    __shared__ float b_s[P];

    int tid = threadIdx.x;
    int wid = tid >> 5, lid = tid & 31;
    int g = lid >> 2, t4 = lid & 3;
    int wm = wid / WN, wn = wid % WN;
    int m_warp = wm * WTM, n_warp = wn * WTN;
    int row0 = blockIdx.x * 64;

    if (tid < P) b_s[tid] = b[tid];

    float acc[MT][NT][4];
#pragma unroll
    for (int i = 0; i < MT; i++)
#pragma unroll
        for (int j = 0; j < NT; j++)
#pragma unroll
            for (int v = 0; v < 4; v++) acc[i][j][v] = 0.f;

    for (int c = 0; c < 8; c++) {
        int k0 = c * 32;
        if (c > 0) __syncthreads();
        // A: 64 rows x 32 k (512 float4 slots / 256 threads = 2 iters)
#pragma unroll
        for (int it = 0; it < 2; it++) {
            int idx = tid + it * 256;
            int m = idx >> 3, q = idx & 7;
            float4 v = make_float4(0.f, 0.f, 0.f, 0.f);
            if (row0 + m < nrows)
                v = *(const float4*)&x[(size_t)(row0 + m) * D + k0 + q * 4];
            uint4 t;
            t.x = f2tf32(v.x); t.y = f2tf32(v.y);
            t.z = f2tf32(v.z); t.w = f2tf32(v.w);
            *(uint4*)&A_s[m][q * 4] = t;
        }
        // B: 192 n x 32 k from the three weight matrices (L2-resident)
#pragma unroll
        for (int it = 0; it < N_TILE * 32 / 256; it++) {
            int i = tid + it * 256;
            int k = i / N_TILE, n = i % N_TILE;
            int seg = n >> 6, nn = n & 63;
            const float* W = (seg == 0) ? Wnt : (seg == 1) ? Wnr : Wst;
            B_s[n][k] = f2tf32(W[(k0 + k) * P + nn]);
        }
        __syncthreads();
#pragma unroll
        for (int ks = 0; ks < 4; ks++) {
            int kk = ks * 8;
            u32 afr[MT][4];
#pragma unroll
            for (int mt = 0; mt < MT; mt++) {
                int m = m_warp + mt * 16 + g;
                afr[mt][0] = A_s[m][kk + t4];
                afr[mt][1] = A_s[m + 8][kk + t4];
                afr[mt][2] = A_s[m][kk + t4 + 4];
                afr[mt][3] = A_s[m + 8][kk + t4 + 4];
            }
            u32 bfr[NT][2];
#pragma unroll
            for (int nt = 0; nt < NT; nt++) {
                int n = n_warp + nt * 8 + g;
                bfr[nt][0] = B_s[n][kk + t4];
                bfr[nt][1] = B_s[n][kk + t4 + 4];
            }
#pragma unroll
            for (int mt = 0; mt < MT; mt++)
#pragma unroll
                for (int nt = 0; nt < NT; nt++)
                    mma_tf32(acc[mt][nt], afr[mt], bfr[nt]);
        }
    }

    __syncthreads();

#pragma unroll
    for (int mt = 0; mt < MT; mt++) {
#pragma unroll
        for (int half = 0; half < 2; half++) {
            int r = row0 + m_warp + mt * 16 + g + half * 8;
            if (r >= nrows) continue;
#pragma unroll
            for (int nt = 0; nt < NT; nt++) {
                int col = n_warp + nt * 8 + t4 * 2;
                int seg = col >> 6, cc = col & 63;
                float v0 = acc[mt][nt][half * 2 + 0];
                float v1 = acc[mt][nt][half * 2 + 1];
                float2 o;
                if (seg == 0) {
                    o.x = v0; o.y = v1;
                    *(float2*)&g_h_tic[(size_t)r * P + cc] = o;
                } else if (seg == 1) {
                    o.x = v0; o.y = v1;
                    *(float2*)&g_h_rel[(size_t)r * P + cc] = o;
                } else {
                    o.x = v0 + b_s[cc]; o.y = v1 + b_s[cc + 1];
                    *(float2*)&out[(size_t)r * P + cc] = o;
                }
            }
        }
    }
}

// ---------------- word self-GEMM (N=64, proven config) ----------------------
__global__ __launch_bounds__(256) void gemm_w(const float* __restrict__ x,
                                              const float* __restrict__ W0,
                                              const float* __restrict__ b,
                                              float* __restrict__ out,
                                              int nrows) {
    constexpr int N_TILE = 64;
    constexpr int WM = 4, WN = 2;
    constexpr int WTM = 128 / WM;       // 32
    constexpr int WTN = N_TILE / WN;    // 32
    constexpr int MT = WTM / 16;        // 2
    constexpr int NT = WTN / 8;         // 4

    __shared__ u32 A_s[128][36];
    __shared__ u32 B_s[N_TILE][36];
    __shared__ float b_s[P];

    int tid = threadIdx.x;
    int wid = tid >> 5, lid = tid & 31;
    int g = lid >> 2, t4 = lid & 3;
    int wm = wid / WN, wn = wid % WN;
    int m_warp = wm * WTM, n_warp = wn * WTN;
    int row0 = blockIdx.x * 128;

    if (tid < P) b_s[tid] = b[tid];

    float acc[MT][NT][4];
#pragma unroll
    for (int i = 0; i < MT; i++)
#pragma unroll
        for (int j = 0; j < NT; j++)
#pragma unroll
            for (int v = 0; v < 4; v++) acc[i][j][v] = 0.f;

    for (int c = 0; c < 8; c++) {
        int k0 = c * 32;
        if (c > 0) __syncthreads();
#pragma unroll
        for (int it = 0; it < 4; it++) {
            int idx = tid + it * 256;
            int m = idx >> 3, q = idx & 7;
            float4 v = make_float4(0.f, 0.f, 0.f, 0.f);
            if (row0 + m < nrows)
                v = *(const float4*)&x[(size_t)(row0 + m) * D + k0 + q * 4];
            uint4 t;
            t.x = f2tf32(v.x); t.y = f2tf32(v.y);
            t.z = f2tf32(v.z); t.w = f2tf32(v.w);
            *(uint4*)&A_s[m][q * 4] = t;
        }
#pragma unroll
        for (int it = 0; it < N_TILE * 32 / 256; it++) {
            int i = tid + it * 256;
            int k = i / N_TILE, n = i % N_TILE;
            B_s[n][k] = f2tf32(W0[(k0 + k) * P + n]);
        }
        __syncthreads();
#pragma unroll
        for (int ks = 0; ks < 4; ks++) {
            int kk = ks * 8;
            u32 afr[MT][4];
#pragma unroll
            for (int mt = 0; mt < MT; mt++) {
                int m = m_warp + mt * 16 + g;
                afr[mt][0] = A_s[m][kk + t4];
                afr[mt][1] = A_s[m + 8][kk + t4];
                afr[mt][2] = A_s[m][kk + t4 + 4];
                afr[mt][3] = A_s[m + 8][kk + t4 + 4];
            }
            u32 bfr[NT][2];
#pragma unroll
            for (int nt = 0; nt < NT; nt++) {
                int n = n_warp + nt * 8 + g;
                bfr[nt][0] = B_s[n][kk + t4];
                bfr[nt][1] = B_s[n][kk + t4 + 4];
            }
#pragma unroll
            for (int mt = 0; mt < MT; mt++)
#pragma unroll
                for (int nt = 0; nt < NT; nt++)
                    mma_tf32(acc[mt][nt], afr[mt], bfr[nt]);
        }
    }

    __syncthreads();

#pragma unroll
    for (int mt = 0; mt < MT; mt++) {
#pragma unroll
        for (int half = 0; half < 2; half++) {
            int r = row0 + m_warp + mt * 16 + g + half * 8;
            if (r >= nrows) continue;
#pragma unroll
            for (int nt = 0; nt < NT; nt++) {
                int col = n_warp + nt * 8 + t4 * 2;
                float v0 = acc[mt][nt][half * 2 + 0] + b_s[col];
                float v1 = acc[mt][nt][half * 2 + 1] + b_s[col + 1];
                float2 o; o.x = v0; o.y = v1;
                *(float2*)&out[(size_t)r * P + col] = o;
            }
        }
    }
}

// ---------------- launch: 3-stream DAG --------------------------------------
// Kernel enqueue order: hist<0>(1), scan1<0>(2), scan2<0>(3),
// gemm_fused3(4) <- ncu-profiled this round (before/after the re-tile).
extern "C" void kernel_launch(void* const* d_in, const int* in_sizes, int n_in,
                              void* d_out, int out_size) {
    const float* x_ac        = (const float*)d_in[0];
    const float* x_w         = (const float*)d_in[1];
    const int*   src_tic     = (const int*)d_in[2];
    const int*   dst_tic     = (const int*)d_in[3];
    const float* w_tic       = (const float*)d_in[4];
    const int*   src_rel     = (const int*)d_in[5];
    const int*   dst_rel     = (const int*)d_in[6];
    const float* w_rel       = (const float*)d_in[7];
    const float* W_self_tic  = (const float*)d_in[8];
    const float* W_neigh_tic = (const float*)d_in[9];
    const float* b_tic       = (const float*)d_in[10];
    const float* W_self_rel  = (const float*)d_in[11];
    const float* W_neigh_rel = (const float*)d_in[12];
    const float* b_rel       = (const float*)d_in[13];
    float* out = (float*)d_out;

    static cudaStream_t s1 = nullptr, s2 = nullptr;
    static cudaEvent_t ev0 = nullptr, evC = nullptr, evH = nullptr,
                       evS1 = nullptr, evD = nullptr;
    static void *p_cnt_tic = nullptr, *p_cnt_rel = nullptr;
    if (s1 == nullptr) {
        cudaStreamCreateWithFlags(&s1, cudaStreamNonBlocking);
        cudaStreamCreateWithFlags(&s2, cudaStreamNonBlocking);
        cudaEventCreateWithFlags(&ev0, cudaEventDisableTiming);
        cudaEventCreateWithFlags(&evC, cudaEventDisableTiming);
        cudaEventCreateWithFlags(&evH, cudaEventDisableTiming);
        cudaEventCreateWithFlags(&evS1, cudaEventDisableTiming);
        cudaEventCreateWithFlags(&evD, cudaEventDisableTiming);
        cudaGetSymbolAddress(&p_cnt_tic, g_cnt_tic);
        cudaGetSymbolAddress(&p_cnt_rel, g_cnt_rel);
    }

    const int GRID_F = (NA + 63) / 64;     // 3125
    const int GRID_W = (NW + 127) / 128;   // 391

    // fork
    cudaEventRecord(ev0, 0);
    cudaStreamWaitEvent(s1, ev0, 0);
    cudaStreamWaitEvent(s2, ev0, 0);

    // s1: tic CSR build head (k1..k3)
    cudaMemsetAsync(p_cnt_tic, 0, NA * sizeof(int), s1);
    hist<0><<<(E_TIC / 4 + 255) / 256, 256, 0, s1>>>(dst_tic, E_TIC);        // k1
    scan1<0><<<NB_TIC, 256, 0, s1>>>();                                       // k2
    scan2<0><<<1, 128, 0, s1>>>();                                            // k3

    // s0: fused x_ac GEMM (k4 -> PROFILED; executes from t=0 on empty s0)
    gemm_fused3<<<GRID_F, 256>>>(x_ac, W_neigh_tic, W_neigh_rel, W_self_tic,
                                 b_tic, out, NA);                             // k4
    cudaEventRecord(evH, 0);

    // s1: finish tic CSR build
    scan3<0><<<NB_TIC, 256, 0, s1>>>();                                       // k5
    reorder<0><<<(E_TIC / 4 + 255) / 256, 256, 0, s1>>>(src_tic, dst_tic,
                                                        w_tic, E_TIC);        // k6
    cudaEventRecord(evC, s1);

    // s0: gather<0> (h_tic by stream order, CSR by evC) -> epi_ac
    cudaStreamWaitEvent(0, evC, 0);
    gather_rows<0><<<(NA + 7) / 8, 256>>>();                                  // k7
    epi_ac<<<(NA * P / 4 + 255) / 256, 256>>>(out);                           // k8

    // s2: word self-GEMM (fully independent)
    gemm_w<<<GRID_W, 256, 0, s2>>>(x_w, W_self_rel, b_rel,
                                   out + (size_t)NA * P, NW);                 // k9
    cudaEventRecord(evS1, s2);

    // s1: rel CSR build, gather<1> (needs h_rel via evH), epi_w
    cudaMemsetAsync(p_cnt_rel, 0, NW * sizeof(int), s1);
    hist<1><<<(E_REL / 4 + 255) / 256, 256, 0, s1>>>(dst_rel, E_REL);         // k10
    scan1<1><<<NB_REL, 256, 0, s1>>>();                                       // k11
    scan2<1><<<1, 128, 0, s1>>>();                                            // k12
    scan3<1><<<NB_REL, 256, 0, s1>>>();                                       // k13
    reorder<1><<<(E_REL / 4 + 255) / 256, 256, 0, s1>>>(src_rel, dst_rel,
                                                        w_rel, E_REL);        // k14
    cudaStreamWaitEvent(s1, evH, 0);
    gather_rows<1><<<(NW + 7) / 8, 256, 0, s1>>>();                           // k15
    cudaStreamWaitEvent(s1, evS1, 0);
    epi_w<<<(NW * (P / 4) + 255) / 256, 256, 0, s1>>>(x_w,
                                                      out + (size_t)NA * P);  // k16

    // join
    cudaEventRecord(evD, s1);
    cudaStreamWaitEvent(0, evD, 0);
}

// round 17
// speedup vs baseline: 2.1522x; 2.1522x over previous
#include <cuda_runtime.h>
#include <cstdint>

#define NA 200000
#define NW 50000
#define D 256
#define P 64
#define E_TIC 4000000
#define E_REL 1000000

#define NB_TIC ((NA + 2047) / 2048)   // 98
#define NB_REL ((NW + 2047) / 2048)   // 25

typedef unsigned long long u64;
typedef unsigned int u32;

// ---------------- scratch (device globals: no allocation allowed) ----------
__device__ float g_h_tic[(size_t)NA * P];
__device__ float g_h_rel[(size_t)NA * P];
__device__ float g_acc_tic[(size_t)NA * P];
__device__ float g_acc_rel[(size_t)NW * P];

__device__ int  g_cnt_tic[NA];
__device__ int  g_cnt_rel[NW];
__device__ int  g_start_tic[NA];
__device__ int  g_start_rel[NW];
__device__ int  g_pos_tic[NA];
__device__ int  g_pos_rel[NW];
__device__ int  g_bsum_tic[128];
__device__ int  g_bsum_rel[128];
__device__ u64  g_csr_tic[E_TIC];           // packed (w<<32 | src)
__device__ u64  g_csr_rel[E_REL];

// ---------------- helpers ---------------------------------------------------
__device__ __forceinline__ u32 f2tf32(float f) {
    u32 o; asm("cvt.rna.tf32.f32 %0, %1;" : "=r"(o) : "f"(f)); return o;
}

__device__ __forceinline__ void mma_tf32(float* c, const u32* a, const u32* b) {
    asm volatile(
        "mma.sync.aligned.m16n8k8.row.col.f32.tf32.tf32.f32 "
        "{%0,%1,%2,%3}, {%4,%5,%6,%7}, {%8,%9}, {%0,%1,%2,%3};"
        : "+f"(c[0]), "+f"(c[1]), "+f"(c[2]), "+f"(c[3])
        : "r"(a[0]), "r"(a[1]), "r"(a[2]), "r"(a[3]), "r"(b[0]), "r"(b[1]));
}

// ---------------- CSR build (R11-proven kernels) ----------------------------
template <int REL>
__global__ __launch_bounds__(256) void hist(const int* __restrict__ dst, int E) {
    int e4 = (blockIdx.x * blockDim.x + threadIdx.x) * 4;
    if (e4 >= E) return;
    int4 d = __ldg((const int4*)&dst[e4]);
    int* cnt = REL ? g_cnt_rel : g_cnt_tic;
    atomicAdd(&cnt[d.x], 1);
    atomicAdd(&cnt[d.y], 1);
    atomicAdd(&cnt[d.z], 1);
    atomicAdd(&cnt[d.w], 1);
}

template <int REL>
__global__ __launch_bounds__(256) void scan1() {
    const int N = REL ? NW : NA;
    const int* cnt = REL ? g_cnt_rel : g_cnt_tic;
    int* start = REL ? g_start_rel : g_start_tic;
    int* bsum = REL ? g_bsum_rel : g_bsum_tic;

    __shared__ int sh[256];
    int t = threadIdx.x;
    int base = blockIdx.x * 2048 + t * 8;
    int v[8]; int s = 0;
#pragma unroll
    for (int j = 0; j < 8; j++) {
        int idx = base + j;
        int c = (idx < N) ? cnt[idx] : 0;
        v[j] = s; s += c;
    }
    sh[t] = s;
    __syncthreads();
    int own = s;
    for (int off = 1; off < 256; off <<= 1) {
        int y = (t >= off) ? sh[t - off] : 0;
        __syncthreads();
        sh[t] += y;
        __syncthreads();
    }
    int texcl = sh[t] - own;
#pragma unroll
    for (int j = 0; j < 8; j++) {
        int idx = base + j;
        if (idx < N) start[idx] = v[j] + texcl;
    }
    if (t == 255) bsum[blockIdx.x] = sh[255];
}

template <int REL>
__global__ __launch_bounds__(128) void scan2() {
    const int NB = REL ? NB_REL : NB_TIC;
    int* bsum = REL ? g_bsum_rel : g_bsum_tic;
    __shared__ int sh[128];
    int t = threadIdx.x;
    int val = (t < NB) ? bsum[t] : 0;
    sh[t] = val;
    __syncthreads();
    for (int off = 1; off < 128; off <<= 1) {
        int y = (t >= off) ? sh[t - off] : 0;
        __syncthreads();
        sh[t] += y;
        __syncthreads();
    }
    if (t < NB) bsum[t] = sh[t] - val;
}

template <int REL>
__global__ __launch_bounds__(256) void scan3() {
    const int N = REL ? NW : NA;
    int* start = REL ? g_start_rel : g_start_tic;
    int* pos = REL ? g_pos_rel : g_pos_tic;
    const int* bsum = REL ? g_bsum_rel : g_bsum_tic;
    int add = bsum[blockIdx.x];
    int base = blockIdx.x * 2048 + threadIdx.x * 8;
#pragma unroll
    for (int j = 0; j < 8; j++) {
        int idx = base + j;
        if (idx < N) {
            int v = start[idx] + add;
            start[idx] = v;
            pos[idx] = v;
        }
    }
}

template <int REL>
__global__ __launch_bounds__(256) void reorder(const int* __restrict__ src,
                                               const int* __restrict__ dst,
                                               const float* __restrict__ we,
                                               int E) {
    int e4 = (blockIdx.x * blockDim.x + threadIdx.x) * 4;
    if (e4 >= E) return;
    int4 d = __ldg((const int4*)&dst[e4]);
    int4 s = __ldg((const int4*)&src[e4]);
    float4 w = __ldg((const float4*)&we[e4]);
    int* pos = REL ? g_pos_rel : g_pos_tic;
    u64* csr = REL ? g_csr_rel : g_csr_tic;
    int p0 = atomicAdd(&pos[d.x], 1);
    int p1 = atomicAdd(&pos[d.y], 1);
    int p2 = atomicAdd(&pos[d.z], 1);
    int p3 = atomicAdd(&pos[d.w], 1);
    csr[p0] = ((u64)__float_as_uint(w.x) << 32) | (u32)s.x;
    csr[p1] = ((u64)__float_as_uint(w.y) << 32) | (u32)s.y;
    csr[p2] = ((u64)__float_as_uint(w.z) << 32) | (u32)s.z;
    csr[p3] = ((u64)__float_as_uint(w.w) << 32) | (u32)s.w;
}

// ---------------- gather (R7 version): warp per dst row, mean ---------------
template <int REL>
__global__ __launch_bounds__(256) void gather_rows() {
    const int N = REL ? NW : NA;
    const int* start = REL ? g_start_rel : g_start_tic;
    const int* cnt = REL ? g_cnt_rel : g_cnt_tic;
    const u64* csr = REL ? g_csr_rel : g_csr_tic;
    const float* h = REL ? g_h_rel : g_h_tic;
    float* acc = REL ? g_acc_rel : g_acc_tic;

    int r = blockIdx.x * 8 + (threadIdx.x >> 5);
    int lid = threadIdx.x & 31;
    if (r >= N) return;
    int beg = start[r];
    int c = cnt[r];
    int end = beg + c;

    float ax = 0.f, ay = 0.f;
    int i = beg;
    for (; i + 4 <= end; i += 4) {
        u64 p0 = __ldg(&csr[i]);
        u64 p1 = __ldg(&csr[i + 1]);
        u64 p2 = __ldg(&csr[i + 2]);
        u64 p3 = __ldg(&csr[i + 3]);
        float2 h0 = *(const float2*)&h[(size_t)(u32)p0 * P + lid * 2];
        float2 h1 = *(const float2*)&h[(size_t)(u32)p1 * P + lid * 2];
        float2 h2 = *(const float2*)&h[(size_t)(u32)p2 * P + lid * 2];
        float2 h3 = *(const float2*)&h[(size_t)(u32)p3 * P + lid * 2];
        float w0 = __uint_as_float((u32)(p0 >> 32));
        float w1 = __uint_as_float((u32)(p1 >> 32));
        float w2 = __uint_as_float((u32)(p2 >> 32));
        float w3 = __uint_as_float((u32)(p3 >> 32));
        ax += h0.x * w0 + h1.x * w1 + h2.x * w2 + h3.x * w3;
        ay += h0.y * w0 + h1.y * w1 + h2.y * w2 + h3.y * w3;
    }
    for (; i < end; i++) {
        u64 p = __ldg(&csr[i]);
        float2 hv = *(const float2*)&h[(size_t)(u32)p * P + lid * 2];
        float w = __uint_as_float((u32)(p >> 32));
        ax += hv.x * w;
        ay += hv.y * w;
    }
    float inv = (c > 0) ? 1.0f / (float)c : 0.0f;
    float2 o; o.x = ax * inv; o.y = ay * inv;
    *(float2*)&acc[(size_t)r * P + lid * 2] = o;
}

// ---------------- epilogues -------------------------------------------------
__global__ __launch_bounds__(256) void epi_ac(float* __restrict__ out) {
    int i = blockIdx.x * blockDim.x + threadIdx.x;
    const int TOT = NA * P / 4;
    if (i >= TOT) return;
    float4 o = ((const float4*)out)[i];
    float4 a = ((const float4*)g_acc_tic)[i];
    o.x += a.x; o.y += a.y; o.z += a.z; o.w += a.w;
    ((float4*)out)[i] = o;
}

__global__ __launch_bounds__(256) void epi_w(const float* __restrict__ x,
                                             float* __restrict__ out) {
    int i = blockIdx.x * blockDim.x + threadIdx.x;
    const int TOT = NW * (P / 4);
    if (i >= TOT) return;
    int r = i >> 4, q = i & 15;
    float4 o = ((const float4*)out)[i];
    float4 a = ((const float4*)g_acc_rel)[i];
    float4 xv = *(const float4*)&x[(size_t)r * D + q * 4];
    o.x = 0.5f * (xv.x + o.x + a.x);
    o.y = 0.5f * (xv.y + o.y + a.y);
    o.z = 0.5f * (xv.z + o.z + a.z);
    o.w = 0.5f * (xv.w + o.w + a.w);
    ((float4*)out)[i] = o;
}

// ---------------- tf32 mma.sync GEMM (R7-proven tiles, no caps) -------------
// MODE 0 (N_TILE=128, WM=2, WN=4): cols [0,64)->g_h_tic, [64,128)->g_h_rel.
//   MT=4, NT=4 -> 64 acc regs. One x_ac pass produces BOTH h matrices.
// MODE 1 (N_TILE=64, WM=4, WN=2): out = x @ W0 + b (raw; epi adds agg).
template <int N_TILE, int MODE, int WM, int WN>
__global__ __launch_bounds__(256) void gemm_mma(const float* __restrict__ x,
                                                const float* __restrict__ W0,
                                                const float* __restrict__ W1,
                                                const float* __restrict__ b,
                                                float* __restrict__ out,
                                                int nrows) {
    constexpr int WTM = 128 / WM;
    constexpr int WTN = N_TILE / WN;
    constexpr int MT = WTM / 16;
    constexpr int NT = WTN / 8;

    __shared__ u32 A_s[128][36];
    __shared__ u32 B_s[N_TILE][36];
    __shared__ float b_s[P];

    int tid = threadIdx.x;
    int wid = tid >> 5, lid = tid & 31;
    int g = lid >> 2, t4 = lid & 3;
    int wm = wid / WN, wn = wid % WN;
    int m_warp = wm * WTM, n_warp = wn * WTN;
    int row0 = blockIdx.x * 128;

    if (MODE == 1 && tid < P) b_s[tid] = b[tid];

    float acc[MT][NT][4];
#pragma unroll
    for (int i = 0; i < MT; i++)
#pragma unroll
        for (int j = 0; j < NT; j++)
#pragma unroll
            for (int v = 0; v < 4; v++) acc[i][j][v] = 0.f;

    for (int c = 0; c < 8; c++) {
        int k0 = c * 32;
        if (c > 0) __syncthreads();
#pragma unroll
        for (int it = 0; it < 4; it++) {
            int idx = tid + it * 256;
            int m = idx >> 3, q = idx & 7;
            float4 v = make_float4(0.f, 0.f, 0.f, 0.f);
            if (row0 + m < nrows)
                v = *(const float4*)&x[(size_t)(row0 + m) * D + k0 + q * 4];
            uint4 t;
            t.x = f2tf32(v.x); t.y = f2tf32(v.y);
            t.z = f2tf32(v.z); t.w = f2tf32(v.w);
            *(uint4*)&A_s[m][q * 4] = t;
        }
#pragma unroll
        for (int it = 0; it < N_TILE * 32 / 256; it++) {
            int i = tid + it * 256;
            int k = i / N_TILE, n = i % N_TILE;
            float w;
            if (MODE == 0)
                w = (n < P) ? W0[(k0 + k) * P + n] : W1[(k0 + k) * P + (n - P)];
            else
                w = W0[(k0 + k) * P + n];
            B_s[n][k] = f2tf32(w);
        }
        __syncthreads();
#pragma unroll
        for (int ks = 0; ks < 4; ks++) {
            int kk = ks * 8;
            u32 afr[MT][4];
#pragma unroll
            for (int mt = 0; mt < MT; mt++) {
                int m = m_warp + mt * 16 + g;
                afr[mt][0] = A_s[m][kk + t4];
                afr[mt][1] = A_s[m + 8][kk + t4];
                afr[mt][2] = A_s[m][kk + t4 + 4];
                afr[mt][3] = A_s[m + 8][kk + t4 + 4];
            }
            u32 bfr[NT][2];
#pragma unroll
            for (int nt = 0; nt < NT; nt++) {
                int n = n_warp + nt * 8 + g;
                bfr[nt][0] = B_s[n][kk + t4];
                bfr[nt][1] = B_s[n][kk + t4 + 4];
            }
#pragma unroll
            for (int mt = 0; mt < MT; mt++)
#pragma unroll
                for (int nt = 0; nt < NT; nt++)
                    mma_tf32(acc[mt][nt], afr[mt], bfr[nt]);
        }
    }

    if (MODE == 1) __syncthreads();

#pragma unroll
    for (int mt = 0; mt < MT; mt++) {
#pragma unroll
        for (int half = 0; half < 2; half++) {
            int r = row0 + m_warp + mt * 16 + g + half * 8;
            if (r >= nrows) continue;
#pragma unroll
            for (int nt = 0; nt < NT; nt++) {
                int col = n_warp + nt * 8 + t4 * 2;
                float v0 = acc[mt][nt][half * 2 + 0];
                float v1 = acc[mt][nt][half * 2 + 1];
                if (MODE == 0) {
                    float* dstb = (col < P) ? g_h_tic : g_h_rel;
                    int cc = col & (P - 1);
                    float2 o; o.x = v0; o.y = v1;
                    *(float2*)&dstb[(size_t)r * P + cc] = o;
                } else {
                    float2 o; o.x = v0 + b_s[col]; o.y = v1 + b_s[col + 1];
                    *(float2*)&out[(size_t)r * P + col] = o;
                }
            }
        }
    }
}

// ---------------- launch: 3-stream DAG --------------------------------------
// Enqueue: hist<0>(1), scan1<0>(2), scan2<0>(3), gemm_mma<128,0>(4)<-PROFILED
extern "C" void kernel_launch(void* const* d_in, const int* in_sizes, int n_in,
                              void* d_out, int out_size) {
    const float* x_ac        = (const float*)d_in[0];
    const float* x_w         = (const float*)d_in[1];
    const int*   src_tic     = (const int*)d_in[2];
    const int*   dst_tic     = (const int*)d_in[3];
    const float* w_tic       = (const float*)d_in[4];
    const int*   src_rel     = (const int*)d_in[5];
    const int*   dst_rel     = (const int*)d_in[6];
    const float* w_rel       = (const float*)d_in[7];
    const float* W_self_tic  = (const float*)d_in[8];
    const float* W_neigh_tic = (const float*)d_in[9];
    const float* b_tic       = (const float*)d_in[10];
    const float* W_self_rel  = (const float*)d_in[11];
    const float* W_neigh_rel = (const float*)d_in[12];
    const float* b_rel       = (const float*)d_in[13];
    float* out = (float*)d_out;

    static cudaStream_t s1 = nullptr, s2 = nullptr;
    static cudaEvent_t ev0 = nullptr, evC = nullptr, evH = nullptr,
                       evS0 = nullptr, evS1 = nullptr, evD = nullptr;
    static void *p_cnt_tic = nullptr, *p_cnt_rel = nullptr;
    if (s1 == nullptr) {
        cudaStreamCreateWithFlags(&s1, cudaStreamNonBlocking);
        cudaStreamCreateWithFlags(&s2, cudaStreamNonBlocking);
        cudaEventCreateWithFlags(&ev0, cudaEventDisableTiming);
        cudaEventCreateWithFlags(&evC, cudaEventDisableTiming);
        cudaEventCreateWithFlags(&evH, cudaEventDisableTiming);
        cudaEventCreateWithFlags(&evS0, cudaEventDisableTiming);
        cudaEventCreateWithFlags(&evS1, cudaEventDisableTiming);
        cudaEventCreateWithFlags(&evD, cudaEventDisableTiming);
        cudaGetSymbolAddress(&p_cnt_tic, g_cnt_tic);
        cudaGetSymbolAddress(&p_cnt_rel, g_cnt_rel);
    }

    const int GRID_A = (NA + 127) / 128;   // 1563
    const int GRID_W = (NW + 127) / 128;   // 391

    // fork
    cudaEventRecord(ev0, 0);
    cudaStreamWaitEvent(s1, ev0, 0);
    cudaStreamWaitEvent(s2, ev0, 0);

    // s1: tic CSR build head
    cudaMemsetAsync(p_cnt_tic, 0, NA * sizeof(int), s1);
    hist<0><<<(E_TIC / 4 + 255) / 256, 256, 0, s1>>>(dst_tic, E_TIC);        // k1
    scan1<0><<<NB_TIC, 256, 0, s1>>>();                                       // k2
    scan2<0><<<1, 128, 0, s1>>>();                                            // k3

    // s0: merged neigh GEMM -> h_tic AND h_rel in one x_ac pass (PROFILED)
    gemm_mma<128, 0, 2, 4><<<GRID_A, 256>>>(x_ac, W_neigh_tic, W_neigh_rel,
                                            nullptr, nullptr, NA);            // k4
    cudaEventRecord(evH, 0);

    // s1: finish tic CSR build
    scan3<0><<<NB_TIC, 256, 0, s1>>>();                                       // k5
    reorder<0><<<(E_TIC / 4 + 255) / 256, 256, 0, s1>>>(src_tic, dst_tic,
                                                        w_tic, E_TIC);        // k6
    cudaEventRecord(evC, s1);

    // s0: gather<0> (h_tic by stream order, CSR by evC) -> epi_ac
    cudaStreamWaitEvent(0, evC, 0);
    gather_rows<0><<<(NA + 7) / 8, 256>>>();                                  // k7

    // s2: self-GEMMs (after neigh GEMM frees the device)
    cudaStreamWaitEvent(s2, evH, 0);
    gemm_mma<64, 1, 4, 2><<<GRID_A, 256, 0, s2>>>(x_ac, W_self_tic, nullptr,
                                                  b_tic, out, NA);            // k8
    cudaEventRecord(evS0, s2);
    gemm_mma<64, 1, 4, 2><<<GRID_W, 256, 0, s2>>>(x_w, W_self_rel, nullptr,
                                                  b_rel,
                                                  out + (size_t)NA * P, NW);  // k9
    cudaEventRecord(evS1, s2);

    cudaStreamWaitEvent(0, evS0, 0);
    epi_ac<<<(NA * P / 4 + 255) / 256, 256>>>(out);                           // k10

    // s1: rel CSR build, gather<1> (needs h_rel via evH), epi_w
    cudaMemsetAsync(p_cnt_rel, 0, NW * sizeof(int), s1);
    hist<1><<<(E_REL / 4 + 255) / 256, 256, 0, s1>>>(dst_rel, E_REL);         // k11
    scan1<1><<<NB_REL, 256, 0, s1>>>();                                       // k12
    scan2<1><<<1, 128, 0, s1>>>();                                            // k13
    scan3<1><<<NB_REL, 256, 0, s1>>>();                                       // k14
    reorder<1><<<(E_REL / 4 + 255) / 256, 256, 0, s1>>>(src_rel, dst_rel,
                                                        w_rel, E_REL);        // k15
    cudaStreamWaitEvent(s1, evH, 0);
    gather_rows<1><<<(NW + 7) / 8, 256, 0, s1>>>();                           // k16
    cudaStreamWaitEvent(s1, evS1, 0);
    epi_w<<<(NW * (P / 4) + 255) / 256, 256, 0, s1>>>(x_w,
                                                      out + (size_t)NA * P);  // k17

    // join
    cudaEventRecord(evD, s1);
    cudaStreamWaitEvent(0, evD, 0);
}